// round 1
// baseline (speedup 1.0000x reference)
#include <cuda_runtime.h>
#include <math.h>

// Problem constants
#define NB    8      // samples
#define Cc    256    // input channels
#define HW    961    // 31*31 spatial positions per sample
#define Mrows 7688   // NB*HW nodes
#define HID   512
#define OUTF  256

// ---------------- scratch (device globals; no allocation allowed) ----------
__device__ float g_S0[NB * Cc];        // per-sample feature sums of x
__device__ float g_Y [Mrows * Cc];     // aggregated input nodes
__device__ float g_H1[Mrows * HID];    // layer1 activations
__device__ float g_P [NB * 8 * HID];   // partial per-sample sums of H1
__device__ float g_S1[NB * HID];       // per-sample sums of H1
__device__ float g_Z [Mrows * HID];    // aggregated H1
__device__ float g_H2[Mrows * OUTF];   // layer2 activations

__device__ __forceinline__ float dinv_of(int b) {
    // deg = 961 (block incl. diag) + 1 (eye) + #neighbor samples (1 or 2)
    int deg = (b == 0 || b == NB - 1) ? 963 : 964;
    return 1.0f / sqrtf((float)deg);
}

// ---------------- per-sample feature sums of x: S0[b][c] = sum_p x[b][c][p]
__global__ void sum_x_kernel(const float* __restrict__ x, float* __restrict__ S0) {
    int bc = blockIdx.x;                 // 0 .. NB*Cc-1
    const float* src = x + (size_t)bc * HW;
    float s = 0.f;
    for (int p = threadIdx.x; p < HW; p += 256) s += src[p];
    __shared__ float red[8];
    #pragma unroll
    for (int off = 16; off; off >>= 1) s += __shfl_down_sync(0xffffffffu, s, off);
    if ((threadIdx.x & 31) == 0) red[threadIdx.x >> 5] = s;
    __syncthreads();
    if (threadIdx.x < 8) {
        s = red[threadIdx.x];
        #pragma unroll
        for (int off = 4; off; off >>= 1) s += __shfl_down_sync(0xffu, s, off);
        if (threadIdx.x == 0) S0[bc] = s;
    }
}

// ---------------- aggregated input: Y[(b,p)][c]
// Y = dinv_b^2 * (S_b + x_i) + sum_{b'=b±1} dinv_b*dinv_b' * x_{(b',p)}
__global__ void agg_x_kernel(const float* __restrict__ x,
                             const float* __restrict__ S0,
                             float* __restrict__ Y) {
    int i = blockIdx.x;                  // node id
    int b = i / HW, p = i % HW;
    int c = threadIdx.x;                 // 0..255
    float db = dinv_of(b);
    float v = db * db * (S0[b * Cc + c] + x[((size_t)(b * Cc + c)) * HW + p]);
    if (b > 0)      v += db * dinv_of(b - 1) * x[((size_t)((b - 1) * Cc + c)) * HW + p];
    if (b < NB - 1) v += db * dinv_of(b + 1) * x[((size_t)((b + 1) * Cc + c)) * HW + p];
    Y[(size_t)i * Cc + c] = v;
}

// ---------------- SGEMM (NT): C[m][n] = lrelu( sum_k A[m][k]*B[n][k] + bias[n] )
// A: [M,K] row-major (K contiguous), B: [N,K] row-major (K contiguous).
// 128x128 block tile, BK=16, 256 threads, 8x8 thread tile.
__global__ __launch_bounds__(256)
void gemm_nt_bias_lrelu(const float* __restrict__ A, const float* __restrict__ B,
                        const float* __restrict__ bias, float* __restrict__ C,
                        int M, int N, int K) {
    __shared__ float As[16][128];
    __shared__ float Bs[16][128];
    const int tid = threadIdx.x;
    const int bm = blockIdx.y * 128;
    const int bn = blockIdx.x * 128;
    const int tx = tid & 15, ty = tid >> 4;

    float acc[8][8];
    #pragma unroll
    for (int i = 0; i < 8; i++)
        #pragma unroll
        for (int j = 0; j < 8; j++) acc[i][j] = 0.f;

    const int lrow = tid >> 2;           // 0..63
    const int lk   = (tid & 3) << 2;     // 0,4,8,12

    for (int k0 = 0; k0 < K; k0 += 16) {
        #pragma unroll
        for (int it = 0; it < 2; it++) {
            int row = lrow + it * 64;
            // A tile (guard M edge)
            int arow = bm + row;
            float4 va = make_float4(0.f, 0.f, 0.f, 0.f);
            if (arow < M) va = *(const float4*)(A + (size_t)arow * K + k0 + lk);
            As[lk + 0][row] = va.x; As[lk + 1][row] = va.y;
            As[lk + 2][row] = va.z; As[lk + 3][row] = va.w;
            // B tile (N is a multiple of 128 here)
            int brow = bn + row;
            float4 vb = *(const float4*)(B + (size_t)brow * K + k0 + lk);
            Bs[lk + 0][row] = vb.x; Bs[lk + 1][row] = vb.y;
            Bs[lk + 2][row] = vb.z; Bs[lk + 3][row] = vb.w;
        }
        __syncthreads();
        #pragma unroll
        for (int k = 0; k < 16; k++) {
            float a[8], bq[8];
            *(float4*)&a[0]  = *(const float4*)&As[k][ty * 8];
            *(float4*)&a[4]  = *(const float4*)&As[k][ty * 8 + 4];
            *(float4*)&bq[0] = *(const float4*)&Bs[k][tx * 8];
            *(float4*)&bq[4] = *(const float4*)&Bs[k][tx * 8 + 4];
            #pragma unroll
            for (int i = 0; i < 8; i++)
                #pragma unroll
                for (int j = 0; j < 8; j++)
                    acc[i][j] += a[i] * bq[j];
        }
        __syncthreads();
    }

    #pragma unroll
    for (int i = 0; i < 8; i++) {
        int row = bm + ty * 8 + i;
        if (row >= M) continue;
        #pragma unroll
        for (int j = 0; j < 8; j++) {
            int col = bn + tx * 8 + j;
            float v = acc[i][j] + bias[col];
            C[(size_t)row * N + col] = (v > 0.f) ? v : 0.01f * v;
        }
    }
}

// ---------------- per-sample partial sums of H1 (deterministic 2-stage)
__global__ void sum_h_part(const float* __restrict__ H, float* __restrict__ P) {
    int b  = blockIdx.x;                       // sample
    int pc = blockIdx.z;                       // p-chunk 0..7
    int f  = blockIdx.y * 128 + threadIdx.x;   // feature
    int p0 = pc * 121;
    int p1 = p0 + 121; if (p1 > HW) p1 = HW;
    float s = 0.f;
    for (int p = p0; p < p1; p++)
        s += H[((size_t)(b * HW + p)) * HID + f];
    P[((size_t)(b * 8 + pc)) * HID + f] = s;
}

__global__ void sum_h_reduce(const float* __restrict__ P, float* __restrict__ S1) {
    int b = blockIdx.x, f = threadIdx.x;       // 512 threads
    float s = 0.f;
    #pragma unroll
    for (int pc = 0; pc < 8; pc++) s += P[((size_t)(b * 8 + pc)) * HID + f];
    S1[b * HID + f] = s;
}

// ---------------- aggregated H1: Z[(b,p)][f]
__global__ void agg_h_kernel(const float* __restrict__ H,
                             const float* __restrict__ S1,
                             float* __restrict__ Z) {
    int i = blockIdx.x;
    int b = i / HW, p = i % HW;
    int f = threadIdx.x;                       // 512 threads
    float db = dinv_of(b);
    float v = db * db * (S1[b * HID + f] + H[(size_t)i * HID + f]);
    if (b > 0)      v += db * dinv_of(b - 1) * H[((size_t)((b - 1) * HW + p)) * HID + f];
    if (b < NB - 1) v += db * dinv_of(b + 1) * H[((size_t)((b + 1) * HW + p)) * HID + f];
    Z[(size_t)i * HID + f] = v;
}

// ---------------- max over samples: out[o][p] = max_b H2[(b,p)][o]
__global__ void max_kernel(const float* __restrict__ H2, float* __restrict__ out) {
    int p = blockIdx.x;                        // 0..960
    int o = threadIdx.x;                       // 0..255
    float m = -INFINITY;
    #pragma unroll
    for (int b = 0; b < NB; b++) {
        float v = H2[((size_t)(b * HW + p)) * OUTF + o];
        m = fmaxf(m, v);
    }
    out[(size_t)o * HW + p] = m;
}

// ---------------- launcher --------------------------------------------------
extern "C" void kernel_launch(void* const* d_in, const int* in_sizes, int n_in,
                              void* d_out, int out_size) {
    const float* x  = (const float*)d_in[0];   // [8,256,31,31]
    const float* W1 = (const float*)d_in[1];   // [512,256]
    const float* b1 = (const float*)d_in[2];   // [512]
    const float* W2 = (const float*)d_in[3];   // [256,512]
    const float* b2 = (const float*)d_in[4];   // [256]
    float* out = (float*)d_out;                // [1,256,31,31]

    float *S0, *Y, *H1, *P, *S1, *Z, *H2;
    cudaGetSymbolAddress((void**)&S0, g_S0);
    cudaGetSymbolAddress((void**)&Y,  g_Y);
    cudaGetSymbolAddress((void**)&H1, g_H1);
    cudaGetSymbolAddress((void**)&P,  g_P);
    cudaGetSymbolAddress((void**)&S1, g_S1);
    cudaGetSymbolAddress((void**)&Z,  g_Z);
    cudaGetSymbolAddress((void**)&H2, g_H2);

    // 1) per-sample sums of x, then analytic graph aggregation -> Y
    sum_x_kernel<<<NB * Cc, 256>>>(x, S0);
    agg_x_kernel<<<Mrows, Cc>>>(x, S0, Y);

    // 2) GEMM1 + bias + leaky_relu: H1 = lrelu(Y @ W1^T + b1)   [7688,512]
    gemm_nt_bias_lrelu<<<dim3(HID / 128, (Mrows + 127) / 128), 256>>>(
        Y, W1, b1, H1, Mrows, HID, Cc);

    // 3) aggregation on H1 -> Z
    sum_h_part<<<dim3(NB, HID / 128, 8), 128>>>(H1, P);
    sum_h_reduce<<<NB, HID>>>(P, S1);
    agg_h_kernel<<<Mrows, HID>>>(H1, S1, Z);

    // 4) GEMM2 + bias + leaky_relu: H2 = lrelu(Z @ W2^T + b2)   [7688,256]
    gemm_nt_bias_lrelu<<<dim3(OUTF / 128, (Mrows + 127) / 128), 256>>>(
        Z, W2, b2, H2, Mrows, OUTF, HID);

    // 5) max over samples -> [1,256,31,31]
    max_kernel<<<HW, OUTF>>>(H2, out);
}